// round 13
// baseline (speedup 1.0000x reference)
#include <cuda_runtime.h>

#define BB 8
#define NN 2048
#define DD 64
#define BN (BB*NN)
#define JSPLIT 8
#define TJ 32
#define BLKR 64
#define NT 8       // j-tiles per block = (NN/JSPLIT)/TJ
#define CST 72     // packed plane row stride (words): 8tg+g conflict-free

// ---------------- device scratch (no allocations allowed) ----------------
__device__ float    g_t1[BN];
__device__ float    g_t2[BN];
__device__ unsigned g_bh[BN/2*DD];     // hw fp16x2 plane, [pair][col]
__device__ int      g_rows[BB][NN];
__device__ int      g_cnt[BB];
__device__ int      g_sem[BB][NN/BLKR];
__device__ float    g_pacc[JSPLIT][BN*DD];
__device__ float    g_pz[JSPLIT][BN];

// ---------------- helpers ----------------
static __device__ __forceinline__ unsigned phf(float lo, float hi) {
    unsigned u;
    asm("cvt.rn.f16x2.f32 %0, %1, %2;" : "=r"(u) : "f"(hi), "f"(lo));
    return u;
}
static __device__ __forceinline__ void mma_f16(float* c, const unsigned* a,
                                               unsigned b0, unsigned b1) {
    asm volatile(
        "mma.sync.aligned.m16n8k16.row.col.f32.f16.f16.f32 "
        "{%0,%1,%2,%3}, {%4,%5,%6,%7}, {%8,%9}, {%0,%1,%2,%3};"
        : "+f"(c[0]), "+f"(c[1]), "+f"(c[2]), "+f"(c[3])
        : "r"(a[0]), "r"(a[1]), "r"(a[2]), "r"(a[3]), "r"(b0), "r"(b1));
}
static __device__ __forceinline__ void cp16(unsigned saddr, const void* gptr) {
    asm volatile("cp.async.ca.shared.global [%0], [%1], 16;"
                 :: "r"(saddr), "l"(gptr));
}
// gated weight: exp(a>0 ? relu(x) : 0); exp(0)=1 covers non-edges
static __device__ __forceinline__ float gw(int a, float x) {
    return __expf((a > 0) ? fmaxf(x, 0.f) : 0.f);
}

// ---------------- kernel 0 ----------------
__global__ void k_reset() {
    int tid = threadIdx.x;
    if (tid < BB) g_cnt[tid] = 0;
    if (tid < BB*(NN/BLKR)) ((int*)g_sem)[tid] = 0;
}

// ---------------- kernel 1: relu(h@W); t1,t2; packed fp16 plane; compact --
__global__ __launch_bounds__(256) void k_prep(
    const float* __restrict__ h, const float* __restrict__ hroot,
    const float* __restrict__ W, const float* __restrict__ a1,
    const float* __restrict__ a2, float* __restrict__ out)
{
    __shared__ float Ws[64*64];
    __shared__ float hs[32*65];
    __shared__ float a1s[64], a2s[64];

    int tid = threadIdx.x;
    int gr0 = blockIdx.x * 32;

    for (int i = tid; i < 64*64/4; i += 256)
        ((float4*)Ws)[i] = ((const float4*)W)[i];
    if (tid < 64) { a1s[tid] = a1[tid]; a2s[tid] = a2[tid]; }
    for (int i = tid; i < 32*64; i += 256) {
        int r = i >> 6, k = i & 63;
        hs[r*65 + k] = h[gr0*64 + i];
    }
    __syncthreads();

    int row = tid >> 3;            // 0..31
    int c0  = (tid & 7) << 3;
    float acc[8];
    #pragma unroll
    for (int c = 0; c < 8; c++) acc[c] = 0.f;

    #pragma unroll 8
    for (int k = 0; k < 64; k++) {
        float hv = hs[row*65 + k];
        float4 w0 = *(float4*)&Ws[k*64 + c0];
        float4 w1 = *(float4*)&Ws[k*64 + c0 + 4];
        acc[0] = fmaf(hv, w0.x, acc[0]);
        acc[1] = fmaf(hv, w0.y, acc[1]);
        acc[2] = fmaf(hv, w0.z, acc[2]);
        acc[3] = fmaf(hv, w0.w, acc[3]);
        acc[4] = fmaf(hv, w1.x, acc[4]);
        acc[5] = fmaf(hv, w1.y, acc[5]);
        acc[6] = fmaf(hv, w1.z, acc[6]);
        acc[7] = fmaf(hv, w1.w, acc[7]);
    }
    #pragma unroll
    for (int c = 0; c < 8; c++) acc[c] = fmaxf(acc[c], 0.f);

    int gr = gr0 + row;

    // ---- packed fp16x2 plane: pair (even row, odd row) ----
    float pv[8];
    #pragma unroll
    for (int c = 0; c < 8; c++)
        pv[c] = __shfl_xor_sync(0xffffffffu, acc[c], 8);
    if (!(row & 1)) {
        unsigned hh[8];
        #pragma unroll
        for (int c = 0; c < 8; c++) hh[c] = phf(acc[c], pv[c]);
        long pb = (long)(gr >> 1)*DD + c0;
        *(uint4*)&g_bh[pb]     = make_uint4(hh[0], hh[1], hh[2], hh[3]);
        *(uint4*)&g_bh[pb + 4] = make_uint4(hh[4], hh[5], hh[6], hh[7]);
    }

    // ---- t1, t2 ----
    float p1 = 0.f, p2 = 0.f;
    #pragma unroll
    for (int c = 0; c < 8; c++) {
        p1 = fmaf(acc[c], a1s[c0 + c], p1);
        p2 = fmaf(acc[c], a2s[c0 + c], p2);
    }
    #pragma unroll
    for (int off = 4; off; off >>= 1) {
        p1 += __shfl_down_sync(0xffffffffu, p1, off, 8);
        p2 += __shfl_down_sync(0xffffffffu, p2, off, 8);
    }
    if ((tid & 7) == 0) { g_t1[gr] = p1; g_t2[gr] = p2; }

    // ---- compaction / passthrough ----
    float hr = hroot[gr];
    if (hr > 0.f) {
        if ((tid & 7) == 0) {
            int b = gr >> 11, n = gr & (NN - 1);
            int idx = atomicAdd(&g_cnt[b], 1);
            g_rows[b][idx] = n;
        }
    } else {
        const float4* hsrc = (const float4*)(h + (long)gr*64 + c0);
        *(float4*)&out[gr*64 + c0]     = hsrc[0];
        *(float4*)&out[gr*64 + c0 + 4] = hsrc[1];
    }
}

// ---------------- kernel 2: pipelined fp16 mma attention + fused reduce --
// 64 rows x 64 cols per block, 4 warps x (16 rows = 1 m-tile, 8 n-tiles).
// JSPLIT=8 j-ranges for occupancy; last finishing split-block of each
// (b, rblock) group reduces partials and writes the normalized output.
__global__ __launch_bounds__(128) void k_attn(const int* __restrict__ adj,
                                              float* __restrict__ out)
{
    __shared__ unsigned bh_s[2][16*CST];      // 2 x 4.6 KB
    __shared__ float    t2_s[NN/JSPLIT];      // 1 KB
    __shared__ int      rn_s[BLKR];
    __shared__ int      ticket_s;

    int b = blockIdx.z;
    int cnt = g_cnt[b];
    int r0 = blockIdx.x << 6;
    if (r0 >= cnt) return;
    int nrows = min(BLKR, cnt - r0);
    int split = blockIdx.y;
    int tid = threadIdx.x, lane = tid & 31, warp = tid >> 5;
    int jbeg = split * (NN / JSPLIT);

    if (tid < BLKR)
        rn_s[tid] = (tid < nrows) ? g_rows[b][r0 + tid] : g_rows[b][r0];
    if (tid < (NN/JSPLIT)/4)
        ((float4*)t2_s)[tid] = ((const float4*)(g_t2 + b*NN + jbeg))[tid];
    __syncthreads();

    int g = lane >> 2, tg = lane & 3;
    int i0 = warp << 4;
    float t1A = g_t1[b*NN + rn_s[i0 + g]];
    float t1B = g_t1[b*NN + rn_s[i0 + g + 8]];

    const int* pA = adj + ((long)(b*NN + rn_s[i0 + g]))*NN + jbeg + (tg << 1);
    const int* pB = adj + ((long)(b*NN + rn_s[i0 + g + 8]))*NN + jbeg + (tg << 1);

    unsigned bhb[2];
    bhb[0] = (unsigned)__cvta_generic_to_shared(&bh_s[0][0]);
    bhb[1] = (unsigned)__cvta_generic_to_shared(&bh_s[1][0]);

    long pbase = (long)(b*NN) >> 1;

    auto stageB = [&](int t) {
        int buf = t & 1;
        int jt = jbeg + t*TJ;
        const uint4* sh = (const uint4*)(g_bh + (pbase + (jt >> 1))*DD);
        #pragma unroll
        for (int k = 0; k < 2; k++) {
            int ci = tid + (k << 7);
            int pair = ci >> 4, col = (ci & 15) << 2;
            cp16(bhb[buf] + (unsigned)((pair*CST + col) << 2), sh + ci);
        }
    };

    int2 nxt[8];
    #pragma unroll
    for (int q = 0; q < 8; q++) {
        int ks = q >> 2, half = (q >> 1) & 1, rb = q & 1;
        const int* p = rb ? pB : pA;
        nxt[q] = *(const int2*)(p + (ks << 4) + (half << 3));
    }

    stageB(0);
    asm volatile("cp.async.commit_group;");
    stageB(1);
    asm volatile("cp.async.commit_group;");

    float acc[8][4];
    #pragma unroll
    for (int nt = 0; nt < 8; nt++)
        #pragma unroll
        for (int q = 0; q < 4; q++) acc[nt][q] = 0.f;
    float zA = 0.f, zB = 0.f;

    for (int t = 0; t < NT; t++) {
        int buf = t & 1;
        int jl = t*TJ;

        int2 cur[8];
        #pragma unroll
        for (int q = 0; q < 8; q++) cur[q] = nxt[q];
        if (t + 1 < NT) {
            int jn = (t + 1)*TJ;
            #pragma unroll
            for (int q = 0; q < 8; q++) {
                int ks = q >> 2, half = (q >> 1) & 1, rb = q & 1;
                const int* p = rb ? pB : pA;
                nxt[q] = *(const int2*)(p + jn + (ks << 4) + (half << 3));
            }
        }

        asm volatile("cp.async.wait_group 1;");
        __syncthreads();

        #pragma unroll
        for (int ks = 0; ks < 2; ks++) {
            int kb0 = (ks << 4) + (tg << 1);
            float2 t2a = *(const float2*)&t2_s[jl + kb0];
            float2 t2b = *(const float2*)&t2_s[jl + kb0 + 8];
            int2 aA0 = cur[(ks << 2) + 0];
            int2 aB0 = cur[(ks << 2) + 1];
            int2 aA1 = cur[(ks << 2) + 2];
            int2 aB1 = cur[(ks << 2) + 3];
            float wA0 = gw(aA0.x, t1A + t2a.x);
            float wA1 = gw(aA0.y, t1A + t2a.y);
            float wA2 = gw(aA1.x, t1A + t2b.x);
            float wA3 = gw(aA1.y, t1A + t2b.y);
            float wB0 = gw(aB0.x, t1B + t2a.x);
            float wB1 = gw(aB0.y, t1B + t2a.y);
            float wB2 = gw(aB1.x, t1B + t2b.x);
            float wB3 = gw(aB1.y, t1B + t2b.y);
            zA += (wA0 + wA1) + (wA2 + wA3);
            zB += (wB0 + wB1) + (wB2 + wB3);
            unsigned am[4];
            am[0] = phf(wA0, wA1);
            am[1] = phf(wB0, wB1);
            am[2] = phf(wA2, wA3);
            am[3] = phf(wB2, wB3);
            #pragma unroll
            for (int nt = 0; nt < 8; nt++) {
                int rk0 = ((ks << 3) + tg)*CST + (nt << 3) + g;
                int rk1 = rk0 + 4*CST;
                mma_f16(acc[nt], am, bh_s[buf][rk0], bh_s[buf][rk1]);
            }
        }
        __syncthreads();
        if (t + 2 < NT) stageB(t + 2);
        asm volatile("cp.async.commit_group;");   // uniform group count
    }

    // ---- z quad-reduce over tg ----
    zA += __shfl_xor_sync(0xffffffffu, zA, 1);
    zA += __shfl_xor_sync(0xffffffffu, zA, 2);
    zB += __shfl_xor_sync(0xffffffffu, zB, 1);
    zB += __shfl_xor_sync(0xffffffffu, zB, 2);
    if (tg == 0) {
        int lA = i0 + g, lB = lA + 8;
        if (lA < nrows) g_pz[split][b*NN + rn_s[lA]] = zA;
        if (lB < nrows) g_pz[split][b*NN + rn_s[lB]] = zB;
    }

    // ---- write partial numerators ----
    {
        float* pz = g_pacc[split];
        int lA = i0 + g, lB = lA + 8;
        if (lA < nrows) {
            float* pa = pz + ((long)(b*NN + rn_s[lA]))*DD + (tg << 1);
            #pragma unroll
            for (int nt = 0; nt < 8; nt++)
                *(float2*)&pa[nt << 3] = make_float2(acc[nt][0], acc[nt][1]);
        }
        if (lB < nrows) {
            float* pa = pz + ((long)(b*NN + rn_s[lB]))*DD + (tg << 1);
            #pragma unroll
            for (int nt = 0; nt < 8; nt++)
                *(float2*)&pa[nt << 3] = make_float2(acc[nt][2], acc[nt][3]);
        }
    }

    // ---- fused reduce: last split-block of this (b, rblock) group ----
    __threadfence();
    __syncthreads();
    if (tid == 0) ticket_s = atomicAdd(&g_sem[b][blockIdx.x], 1);
    __syncthreads();
    if (ticket_s == JSPLIT - 1) {
        int li = tid >> 1;
        if (li < nrows) {
            long base = (long)b*NN + rn_s[li];
            float z = 0.f;
            #pragma unroll
            for (int s = 0; s < JSPLIT; s++) z += g_pz[s][base];
            float inv = __fdividef(1.f, z);
            long o = base*DD + ((tid & 1) << 5);
            float vr[32];
            #pragma unroll
            for (int q = 0; q < 32; q++) vr[q] = 0.f;
            #pragma unroll
            for (int s = 0; s < JSPLIT; s++) {
                const float4* p = (const float4*)&g_pacc[s][o];
                #pragma unroll
                for (int q = 0; q < 8; q++) {
                    float4 v = p[q];
                    vr[4*q]   += v.x; vr[4*q+1] += v.y;
                    vr[4*q+2] += v.z; vr[4*q+3] += v.w;
                }
            }
            float* po = out + o;
            #pragma unroll
            for (int q = 0; q < 8; q++)
                *(float4*)&po[4*q] = make_float4(vr[4*q]*inv, vr[4*q+1]*inv,
                                                 vr[4*q+2]*inv, vr[4*q+3]*inv);
        }
    }
}

// ---------------- launch ----------------
extern "C" void kernel_launch(void* const* d_in, const int* in_sizes, int n_in,
                              void* d_out, int out_size)
{
    const float* h     = (const float*)d_in[0];
    const int*   adj   = (const int*)  d_in[1];
    const float* hroot = (const float*)d_in[2];
    const float* W     = (const float*)d_in[3];
    const float* a1    = (const float*)d_in[4];
    const float* a2    = (const float*)d_in[5];
    float* out = (float*)d_out;

    k_reset<<<1, 256>>>();
    k_prep<<<BN/32, 256>>>(h, hroot, W, a1, a2, out);
    k_attn<<<dim3(NN/BLKR, JSPLIT, BB), 128>>>(adj, out);
}

// round 14
// speedup vs baseline: 1.5086x; 1.5086x over previous
#include <cuda_runtime.h>

#define BB 8
#define NN 2048
#define DD 64
#define BN (BB*NN)
#define JSPLIT 8
#define TJ 32
#define BLKR 64
#define NT 8       // j-tiles per block = (NN/JSPLIT)/TJ
#define CST 72     // packed plane row stride (words): 8tg+g conflict-free

// ---------------- device scratch (no allocations allowed) ----------------
__device__ float    g_t1[BN];
__device__ float    g_t2[BN];
__device__ unsigned g_bh[BN/2*DD];     // hw fp16x2 plane, [pair][col]
__device__ int      g_rows[BB][NN];
__device__ int      g_cnt[BB];
__device__ float    g_pacc[JSPLIT][BN*DD];
__device__ float    g_pz[JSPLIT][BN];

// ---------------- helpers ----------------
static __device__ __forceinline__ unsigned phf(float lo, float hi) {
    unsigned u;
    asm("cvt.rn.f16x2.f32 %0, %1, %2;" : "=r"(u) : "f"(hi), "f"(lo));
    return u;
}
static __device__ __forceinline__ void mma_f16(float* c, const unsigned* a,
                                               unsigned b0, unsigned b1) {
    asm volatile(
        "mma.sync.aligned.m16n8k16.row.col.f32.f16.f16.f32 "
        "{%0,%1,%2,%3}, {%4,%5,%6,%7}, {%8,%9}, {%0,%1,%2,%3};"
        : "+f"(c[0]), "+f"(c[1]), "+f"(c[2]), "+f"(c[3])
        : "r"(a[0]), "r"(a[1]), "r"(a[2]), "r"(a[3]), "r"(b0), "r"(b1));
}
static __device__ __forceinline__ void cp16(unsigned saddr, const void* gptr) {
    asm volatile("cp.async.ca.shared.global [%0], [%1], 16;"
                 :: "r"(saddr), "l"(gptr));
}
// gated weight: exp(a>0 ? relu(x) : 0); exp(0)=1 covers non-edges
static __device__ __forceinline__ float gw(int a, float x) {
    return __expf((a > 0) ? fmaxf(x, 0.f) : 0.f);
}

// ---------------- kernel 0 ----------------
__global__ void k_reset() {
    if (threadIdx.x < BB) g_cnt[threadIdx.x] = 0;
}

// ---------------- kernel 1: relu(h@W); t1,t2; packed fp16 plane; compact --
__global__ __launch_bounds__(256) void k_prep(
    const float* __restrict__ h, const float* __restrict__ hroot,
    const float* __restrict__ W, const float* __restrict__ a1,
    const float* __restrict__ a2, float* __restrict__ out)
{
    __shared__ float Ws[64*64];
    __shared__ float hs[32*65];
    __shared__ float a1s[64], a2s[64];

    int tid = threadIdx.x;
    int gr0 = blockIdx.x * 32;

    for (int i = tid; i < 64*64/4; i += 256)
        ((float4*)Ws)[i] = ((const float4*)W)[i];
    if (tid < 64) { a1s[tid] = a1[tid]; a2s[tid] = a2[tid]; }
    for (int i = tid; i < 32*64; i += 256) {
        int r = i >> 6, k = i & 63;
        hs[r*65 + k] = h[gr0*64 + i];
    }
    __syncthreads();

    int row = tid >> 3;            // 0..31
    int c0  = (tid & 7) << 3;
    float acc[8];
    #pragma unroll
    for (int c = 0; c < 8; c++) acc[c] = 0.f;

    #pragma unroll 8
    for (int k = 0; k < 64; k++) {
        float hv = hs[row*65 + k];
        float4 w0 = *(float4*)&Ws[k*64 + c0];
        float4 w1 = *(float4*)&Ws[k*64 + c0 + 4];
        acc[0] = fmaf(hv, w0.x, acc[0]);
        acc[1] = fmaf(hv, w0.y, acc[1]);
        acc[2] = fmaf(hv, w0.z, acc[2]);
        acc[3] = fmaf(hv, w0.w, acc[3]);
        acc[4] = fmaf(hv, w1.x, acc[4]);
        acc[5] = fmaf(hv, w1.y, acc[5]);
        acc[6] = fmaf(hv, w1.z, acc[6]);
        acc[7] = fmaf(hv, w1.w, acc[7]);
    }
    #pragma unroll
    for (int c = 0; c < 8; c++) acc[c] = fmaxf(acc[c], 0.f);

    int gr = gr0 + row;

    // ---- packed fp16x2 plane: pair (even row, odd row) ----
    float pv[8];
    #pragma unroll
    for (int c = 0; c < 8; c++)
        pv[c] = __shfl_xor_sync(0xffffffffu, acc[c], 8);
    if (!(row & 1)) {
        unsigned hh[8];
        #pragma unroll
        for (int c = 0; c < 8; c++) hh[c] = phf(acc[c], pv[c]);
        long pb = (long)(gr >> 1)*DD + c0;
        *(uint4*)&g_bh[pb]     = make_uint4(hh[0], hh[1], hh[2], hh[3]);
        *(uint4*)&g_bh[pb + 4] = make_uint4(hh[4], hh[5], hh[6], hh[7]);
    }

    // ---- t1, t2 ----
    float p1 = 0.f, p2 = 0.f;
    #pragma unroll
    for (int c = 0; c < 8; c++) {
        p1 = fmaf(acc[c], a1s[c0 + c], p1);
        p2 = fmaf(acc[c], a2s[c0 + c], p2);
    }
    #pragma unroll
    for (int off = 4; off; off >>= 1) {
        p1 += __shfl_down_sync(0xffffffffu, p1, off, 8);
        p2 += __shfl_down_sync(0xffffffffu, p2, off, 8);
    }
    if ((tid & 7) == 0) { g_t1[gr] = p1; g_t2[gr] = p2; }

    // ---- compaction / passthrough ----
    float hr = hroot[gr];
    if (hr > 0.f) {
        if ((tid & 7) == 0) {
            int b = gr >> 11, n = gr & (NN - 1);
            int idx = atomicAdd(&g_cnt[b], 1);
            g_rows[b][idx] = n;
        }
    } else {
        const float4* hsrc = (const float4*)(h + (long)gr*64 + c0);
        *(float4*)&out[gr*64 + c0]     = hsrc[0];
        *(float4*)&out[gr*64 + c0 + 4] = hsrc[1];
    }
}

// ---------------- kernel 2: pipelined fp16 mma attention GEMM ------------
// 64 rows x 64 cols per block, 4 warps x (16 rows = 1 m-tile, 8 n-tiles).
// JSPLIT=8 j-ranges for occupancy (~7 warps/SMSP active). B plane triple-
// buffered via cp.async -> ONE __syncthreads per tile. adj prefetched to
// registers one tile ahead; t2 staged once per block.
__global__ __launch_bounds__(128) void k_attn(const int* __restrict__ adj)
{
    __shared__ unsigned bh_s[3][16*CST];      // 3 x 4.6 KB
    __shared__ float    t2_s[NN/JSPLIT];      // 1 KB
    __shared__ int      rn_s[BLKR];

    int b = blockIdx.z;
    int cnt = g_cnt[b];
    int r0 = blockIdx.x << 6;
    if (r0 >= cnt) return;
    int nrows = min(BLKR, cnt - r0);
    int split = blockIdx.y;
    int tid = threadIdx.x, lane = tid & 31, warp = tid >> 5;
    int jbeg = split * (NN / JSPLIT);

    if (tid < BLKR)
        rn_s[tid] = (tid < nrows) ? g_rows[b][r0 + tid] : g_rows[b][r0];
    if (tid < (NN/JSPLIT)/4)
        ((float4*)t2_s)[tid] = ((const float4*)(g_t2 + b*NN + jbeg))[tid];
    __syncthreads();

    int g = lane >> 2, tg = lane & 3;
    int i0 = warp << 4;
    float t1A = g_t1[b*NN + rn_s[i0 + g]];
    float t1B = g_t1[b*NN + rn_s[i0 + g + 8]];

    const int* pA = adj + ((long)(b*NN + rn_s[i0 + g]))*NN + jbeg + (tg << 1);
    const int* pB = adj + ((long)(b*NN + rn_s[i0 + g + 8]))*NN + jbeg + (tg << 1);

    unsigned bhb[3];
    #pragma unroll
    for (int u = 0; u < 3; u++)
        bhb[u] = (unsigned)__cvta_generic_to_shared(&bh_s[u][0]);

    long pbase = (long)(b*NN) >> 1;

    auto stageB = [&](int t) {
        int buf = t % 3;
        int jt = jbeg + t*TJ;
        const uint4* sh = (const uint4*)(g_bh + (pbase + (jt >> 1))*DD);
        #pragma unroll
        for (int k = 0; k < 2; k++) {
            int ci = tid + (k << 7);
            int pair = ci >> 4, col = (ci & 15) << 2;
            cp16(bhb[buf] + (unsigned)((pair*CST + col) << 2), sh + ci);
        }
    };

    int2 nxt[8];
    #pragma unroll
    for (int q = 0; q < 8; q++) {
        int ks = q >> 2, half = (q >> 1) & 1, rb = q & 1;
        const int* p = rb ? pB : pA;
        nxt[q] = *(const int2*)(p + (ks << 4) + (half << 3));
    }

    stageB(0);
    asm volatile("cp.async.commit_group;");
    stageB(1);
    asm volatile("cp.async.commit_group;");

    float acc[8][4];
    #pragma unroll
    for (int nt = 0; nt < 8; nt++)
        #pragma unroll
        for (int q = 0; q < 4; q++) acc[nt][q] = 0.f;
    float zA = 0.f, zB = 0.f;

    for (int t = 0; t < NT; t++) {
        int buf = t % 3;
        int jl = t*TJ;

        int2 cur[8];
        #pragma unroll
        for (int q = 0; q < 8; q++) cur[q] = nxt[q];
        if (t + 1 < NT) {
            int jn = (t + 1)*TJ;
            #pragma unroll
            for (int q = 0; q < 8; q++) {
                int ks = q >> 2, half = (q >> 1) & 1, rb = q & 1;
                const int* p = rb ? pB : pA;
                nxt[q] = *(const int2*)(p + jn + (ks << 4) + (half << 3));
            }
        }

        // group t must be complete (group t+1 may be pending)
        asm volatile("cp.async.wait_group 1;");
        __syncthreads();   // single barrier per tile (triple buffer)

        #pragma unroll
        for (int ks = 0; ks < 2; ks++) {
            int kb0 = (ks << 4) + (tg << 1);
            float2 t2a = *(const float2*)&t2_s[jl + kb0];
            float2 t2b = *(const float2*)&t2_s[jl + kb0 + 8];
            int2 aA0 = cur[(ks << 2) + 0];
            int2 aB0 = cur[(ks << 2) + 1];
            int2 aA1 = cur[(ks << 2) + 2];
            int2 aB1 = cur[(ks << 2) + 3];
            float wA0 = gw(aA0.x, t1A + t2a.x);
            float wA1 = gw(aA0.y, t1A + t2a.y);
            float wA2 = gw(aA1.x, t1A + t2b.x);
            float wA3 = gw(aA1.y, t1A + t2b.y);
            float wB0 = gw(aB0.x, t1B + t2a.x);
            float wB1 = gw(aB0.y, t1B + t2a.y);
            float wB2 = gw(aB1.x, t1B + t2b.x);
            float wB3 = gw(aB1.y, t1B + t2b.y);
            zA += (wA0 + wA1) + (wA2 + wA3);
            zB += (wB0 + wB1) + (wB2 + wB3);
            unsigned am[4];
            am[0] = phf(wA0, wA1);
            am[1] = phf(wB0, wB1);
            am[2] = phf(wA2, wA3);
            am[3] = phf(wB2, wB3);
            #pragma unroll
            for (int nt = 0; nt < 8; nt++) {
                int rk0 = ((ks << 3) + tg)*CST + (nt << 3) + g;
                int rk1 = rk0 + 4*CST;
                mma_f16(acc[nt], am, bh_s[buf][rk0], bh_s[buf][rk1]);
            }
        }
        // stage t+2 into buffer (t+2)%3: consumed last at tile t-1; the
        // barrier above guarantees every warp has left tile t-1.
        if (t + 2 < NT) stageB(t + 2);
        asm volatile("cp.async.commit_group;");   // uniform group count
    }

    // ---- z quad-reduce over tg ----
    zA += __shfl_xor_sync(0xffffffffu, zA, 1);
    zA += __shfl_xor_sync(0xffffffffu, zA, 2);
    zB += __shfl_xor_sync(0xffffffffu, zB, 1);
    zB += __shfl_xor_sync(0xffffffffu, zB, 2);
    if (tg == 0) {
        int lA = i0 + g, lB = lA + 8;
        if (lA < nrows) g_pz[split][b*NN + rn_s[lA]] = zA;
        if (lB < nrows) g_pz[split][b*NN + rn_s[lB]] = zB;
    }

    // ---- write partial numerators ----
    float* pz = g_pacc[split];
    int lA = i0 + g, lB = lA + 8;
    if (lA < nrows) {
        float* pa = pz + ((long)(b*NN + rn_s[lA]))*DD + (tg << 1);
        #pragma unroll
        for (int nt = 0; nt < 8; nt++)
            *(float2*)&pa[nt << 3] = make_float2(acc[nt][0], acc[nt][1]);
    }
    if (lB < nrows) {
        float* pa = pz + ((long)(b*NN + rn_s[lB]))*DD + (tg << 1);
        #pragma unroll
        for (int nt = 0; nt < 8; nt++)
            *(float2*)&pa[nt << 3] = make_float2(acc[nt][2], acc[nt][3]);
    }
}

// ---------------- kernel 3: reduce partials, normalize, write out --------
__global__ __launch_bounds__(256) void k_reduce(float* __restrict__ out)
{
    int b = blockIdx.y;
    int k = blockIdx.x * 8 + (threadIdx.x >> 5);
    if (k >= g_cnt[b]) return;
    int lane = threadIdx.x & 31;
    int n = g_rows[b][k];
    long base = (long)b*NN + n;

    float z = 0.f;
    #pragma unroll
    for (int s = 0; s < JSPLIT; s++) z += g_pz[s][base];
    float inv = __fdividef(1.0f, z);

    long o = base*DD + lane*2;
    float vx = 0.f, vy = 0.f;
    #pragma unroll
    for (int s = 0; s < JSPLIT; s++) {
        float2 p = *(const float2*)&g_pacc[s][o];
        vx += p.x; vy += p.y;
    }
    *(float2*)&out[o] = make_float2(vx * inv, vy * inv);
}

// ---------------- launch ----------------
extern "C" void kernel_launch(void* const* d_in, const int* in_sizes, int n_in,
                              void* d_out, int out_size)
{
    const float* h     = (const float*)d_in[0];
    const int*   adj   = (const int*)  d_in[1];
    const float* hroot = (const float*)d_in[2];
    const float* W     = (const float*)d_in[3];
    const float* a1    = (const float*)d_in[4];
    const float* a2    = (const float*)d_in[5];
    float* out = (float*)d_out;

    k_reset<<<1, 32>>>();
    k_prep<<<BN/32, 256>>>(h, hroot, W, a1, a2, out);
    k_attn<<<dim3(NN/BLKR, JSPLIT, BB), 128>>>(adj);
    k_reduce<<<dim3(NN/8, BB), 256>>>(out);
}

// round 15
// speedup vs baseline: 1.5707x; 1.0412x over previous
#include <cuda_runtime.h>

#define BB 8
#define NN 2048
#define DD 64
#define BN (BB*NN)
#define JSPLIT 8
#define TJ 32
#define BLKR 64
#define NT 8       // j-tiles per block = (NN/JSPLIT)/TJ
#define CST 72     // packed plane row stride (words): 8tg+g conflict-free

// ---------------- device scratch (no allocations allowed) ----------------
__device__ float    g_e1[BN];          // exp(t1)
__device__ float    g_e2[BN];          // exp(t2)
__device__ unsigned g_bh[BN/2*DD];     // hw fp16x2 plane, [pair][col]
__device__ int      g_rows[BB][NN];
__device__ int      g_cnt[BB];
__device__ float    g_pacc[JSPLIT][BN*DD];
__device__ float    g_pz[JSPLIT][BN];

// ---------------- helpers ----------------
static __device__ __forceinline__ unsigned phf(float lo, float hi) {
    unsigned u;
    asm("cvt.rn.f16x2.f32 %0, %1, %2;" : "=r"(u) : "f"(hi), "f"(lo));
    return u;
}
static __device__ __forceinline__ void mma_f16(float* c, const unsigned* a,
                                               unsigned b0, unsigned b1) {
    asm volatile(
        "mma.sync.aligned.m16n8k16.row.col.f32.f16.f16.f32 "
        "{%0,%1,%2,%3}, {%4,%5,%6,%7}, {%8,%9}, {%0,%1,%2,%3};"
        : "+f"(c[0]), "+f"(c[1]), "+f"(c[2]), "+f"(c[3])
        : "r"(a[0]), "r"(a[1]), "r"(a[2]), "r"(a[3]), "r"(b0), "r"(b1));
}
static __device__ __forceinline__ void cp16(unsigned saddr, const void* gptr) {
    asm volatile("cp.async.ca.shared.global [%0], [%1], 16;"
                 :: "r"(saddr), "l"(gptr));
}
// gated weight: adj>0 ? max(E1*E2, 1) : 1   (x>0 <=> E1*E2>1, exp monotone)
static __device__ __forceinline__ float gw(int a, float p) {
    return (a > 0) ? fmaxf(p, 1.f) : 1.f;
}

// ---------------- kernel 0 ----------------
__global__ void k_reset() {
    if (threadIdx.x < BB) g_cnt[threadIdx.x] = 0;
}

// ---------------- kernel 1: relu(h@W); exp(t1),exp(t2); fp16 plane; compact
__global__ __launch_bounds__(256) void k_prep(
    const float* __restrict__ h, const float* __restrict__ hroot,
    const float* __restrict__ W, const float* __restrict__ a1,
    const float* __restrict__ a2, float* __restrict__ out)
{
    __shared__ float Ws[64*64];
    __shared__ float hs[32*65];
    __shared__ float a1s[64], a2s[64];

    int tid = threadIdx.x;
    int gr0 = blockIdx.x * 32;

    for (int i = tid; i < 64*64/4; i += 256)
        ((float4*)Ws)[i] = ((const float4*)W)[i];
    if (tid < 64) { a1s[tid] = a1[tid]; a2s[tid] = a2[tid]; }
    for (int i = tid; i < 32*64; i += 256) {
        int r = i >> 6, k = i & 63;
        hs[r*65 + k] = h[gr0*64 + i];
    }
    __syncthreads();

    int row = tid >> 3;            // 0..31
    int c0  = (tid & 7) << 3;
    float acc[8];
    #pragma unroll
    for (int c = 0; c < 8; c++) acc[c] = 0.f;

    #pragma unroll 8
    for (int k = 0; k < 64; k++) {
        float hv = hs[row*65 + k];
        float4 w0 = *(float4*)&Ws[k*64 + c0];
        float4 w1 = *(float4*)&Ws[k*64 + c0 + 4];
        acc[0] = fmaf(hv, w0.x, acc[0]);
        acc[1] = fmaf(hv, w0.y, acc[1]);
        acc[2] = fmaf(hv, w0.z, acc[2]);
        acc[3] = fmaf(hv, w0.w, acc[3]);
        acc[4] = fmaf(hv, w1.x, acc[4]);
        acc[5] = fmaf(hv, w1.y, acc[5]);
        acc[6] = fmaf(hv, w1.z, acc[6]);
        acc[7] = fmaf(hv, w1.w, acc[7]);
    }
    #pragma unroll
    for (int c = 0; c < 8; c++) acc[c] = fmaxf(acc[c], 0.f);

    int gr = gr0 + row;

    // ---- packed fp16x2 plane: pair (even row, odd row) ----
    float pv[8];
    #pragma unroll
    for (int c = 0; c < 8; c++)
        pv[c] = __shfl_xor_sync(0xffffffffu, acc[c], 8);
    if (!(row & 1)) {
        unsigned hh[8];
        #pragma unroll
        for (int c = 0; c < 8; c++) hh[c] = phf(acc[c], pv[c]);
        long pb = (long)(gr >> 1)*DD + c0;
        *(uint4*)&g_bh[pb]     = make_uint4(hh[0], hh[1], hh[2], hh[3]);
        *(uint4*)&g_bh[pb + 4] = make_uint4(hh[4], hh[5], hh[6], hh[7]);
    }

    // ---- exp(t1), exp(t2) ----
    float p1 = 0.f, p2 = 0.f;
    #pragma unroll
    for (int c = 0; c < 8; c++) {
        p1 = fmaf(acc[c], a1s[c0 + c], p1);
        p2 = fmaf(acc[c], a2s[c0 + c], p2);
    }
    #pragma unroll
    for (int off = 4; off; off >>= 1) {
        p1 += __shfl_down_sync(0xffffffffu, p1, off, 8);
        p2 += __shfl_down_sync(0xffffffffu, p2, off, 8);
    }
    if ((tid & 7) == 0) { g_e1[gr] = __expf(p1); g_e2[gr] = __expf(p2); }

    // ---- compaction / passthrough ----
    float hr = hroot[gr];
    if (hr > 0.f) {
        if ((tid & 7) == 0) {
            int b = gr >> 11, n = gr & (NN - 1);
            int idx = atomicAdd(&g_cnt[b], 1);
            g_rows[b][idx] = n;
        }
    } else {
        const float4* hsrc = (const float4*)(h + (long)gr*64 + c0);
        *(float4*)&out[gr*64 + c0]     = hsrc[0];
        *(float4*)&out[gr*64 + c0 + 4] = hsrc[1];
    }
}

// ---------------- kernel 2: pipelined fp16 mma attention GEMM ------------
// 64 rows x 64 cols per block, 4 warps x (16 rows = 1 m-tile, 8 n-tiles).
// Weight path is MUFU-free: w = adj>0 ? max(E1*E2, 1) : 1. B plane triple-
// buffered via cp.async; adj prefetched (streaming) one tile ahead.
__global__ __launch_bounds__(128) void k_attn(const int* __restrict__ adj)
{
    __shared__ unsigned bh_s[3][16*CST];      // 3 x 4.6 KB
    __shared__ float    e2_s[NN/JSPLIT];      // 1 KB
    __shared__ int      rn_s[BLKR];

    int b = blockIdx.z;
    int cnt = g_cnt[b];
    int r0 = blockIdx.x << 6;
    if (r0 >= cnt) return;
    int nrows = min(BLKR, cnt - r0);
    int split = blockIdx.y;
    int tid = threadIdx.x, lane = tid & 31, warp = tid >> 5;
    int jbeg = split * (NN / JSPLIT);

    if (tid < BLKR)
        rn_s[tid] = (tid < nrows) ? g_rows[b][r0 + tid] : g_rows[b][r0];
    if (tid < (NN/JSPLIT)/4)
        ((float4*)e2_s)[tid] = ((const float4*)(g_e2 + b*NN + jbeg))[tid];
    __syncthreads();

    int g = lane >> 2, tg = lane & 3;
    int i0 = warp << 4;
    float E1A = g_e1[b*NN + rn_s[i0 + g]];
    float E1B = g_e1[b*NN + rn_s[i0 + g + 8]];

    const int* pA = adj + ((long)(b*NN + rn_s[i0 + g]))*NN + jbeg + (tg << 1);
    const int* pB = adj + ((long)(b*NN + rn_s[i0 + g + 8]))*NN + jbeg + (tg << 1);

    unsigned bhb[3];
    #pragma unroll
    for (int u = 0; u < 3; u++)
        bhb[u] = (unsigned)__cvta_generic_to_shared(&bh_s[u][0]);

    long pbase = (long)(b*NN) >> 1;

    auto stageB = [&](int t) {
        int buf = t % 3;
        int jt = jbeg + t*TJ;
        const uint4* sh = (const uint4*)(g_bh + (pbase + (jt >> 1))*DD);
        #pragma unroll
        for (int k = 0; k < 2; k++) {
            int ci = tid + (k << 7);
            int pair = ci >> 4, col = (ci & 15) << 2;
            cp16(bhb[buf] + (unsigned)((pair*CST + col) << 2), sh + ci);
        }
    };

    int2 nxt[8];
    #pragma unroll
    for (int q = 0; q < 8; q++) {
        int ks = q >> 2, half = (q >> 1) & 1, rb = q & 1;
        const int* p = rb ? pB : pA;
        nxt[q] = __ldcs((const int2*)(p + (ks << 4) + (half << 3)));
    }

    stageB(0);
    asm volatile("cp.async.commit_group;");
    stageB(1);
    asm volatile("cp.async.commit_group;");

    float acc[8][4];
    #pragma unroll
    for (int nt = 0; nt < 8; nt++)
        #pragma unroll
        for (int q = 0; q < 4; q++) acc[nt][q] = 0.f;
    float zA = 0.f, zB = 0.f;

    for (int t = 0; t < NT; t++) {
        int buf = t % 3;
        int jl = t*TJ;

        int2 cur[8];
        #pragma unroll
        for (int q = 0; q < 8; q++) cur[q] = nxt[q];
        if (t + 1 < NT) {
            int jn = (t + 1)*TJ;
            #pragma unroll
            for (int q = 0; q < 8; q++) {
                int ks = q >> 2, half = (q >> 1) & 1, rb = q & 1;
                const int* p = rb ? pB : pA;
                nxt[q] = __ldcs((const int2*)(p + jn + (ks << 4) + (half << 3)));
            }
        }

        asm volatile("cp.async.wait_group 1;");
        __syncthreads();   // single barrier per tile (triple buffer)

        #pragma unroll
        for (int ks = 0; ks < 2; ks++) {
            int kb0 = (ks << 4) + (tg << 1);
            float2 e2a = *(const float2*)&e2_s[jl + kb0];
            float2 e2b = *(const float2*)&e2_s[jl + kb0 + 8];
            int2 aA0 = cur[(ks << 2) + 0];
            int2 aB0 = cur[(ks << 2) + 1];
            int2 aA1 = cur[(ks << 2) + 2];
            int2 aB1 = cur[(ks << 2) + 3];
            float wA0 = gw(aA0.x, E1A*e2a.x);
            float wA1 = gw(aA0.y, E1A*e2a.y);
            float wA2 = gw(aA1.x, E1A*e2b.x);
            float wA3 = gw(aA1.y, E1A*e2b.y);
            float wB0 = gw(aB0.x, E1B*e2a.x);
            float wB1 = gw(aB0.y, E1B*e2a.y);
            float wB2 = gw(aB1.x, E1B*e2b.x);
            float wB3 = gw(aB1.y, E1B*e2b.y);
            zA += (wA0 + wA1) + (wA2 + wA3);
            zB += (wB0 + wB1) + (wB2 + wB3);
            unsigned am[4];
            am[0] = phf(wA0, wA1);
            am[1] = phf(wB0, wB1);
            am[2] = phf(wA2, wA3);
            am[3] = phf(wB2, wB3);
            #pragma unroll
            for (int nt = 0; nt < 8; nt++) {
                int rk0 = ((ks << 3) + tg)*CST + (nt << 3) + g;
                int rk1 = rk0 + 4*CST;
                mma_f16(acc[nt], am, bh_s[buf][rk0], bh_s[buf][rk1]);
            }
        }
        if (t + 2 < NT) stageB(t + 2);
        asm volatile("cp.async.commit_group;");   // uniform group count
    }

    // ---- z quad-reduce over tg ----
    zA += __shfl_xor_sync(0xffffffffu, zA, 1);
    zA += __shfl_xor_sync(0xffffffffu, zA, 2);
    zB += __shfl_xor_sync(0xffffffffu, zB, 1);
    zB += __shfl_xor_sync(0xffffffffu, zB, 2);
    if (tg == 0) {
        int lA = i0 + g, lB = lA + 8;
        if (lA < nrows) g_pz[split][b*NN + rn_s[lA]] = zA;
        if (lB < nrows) g_pz[split][b*NN + rn_s[lB]] = zB;
    }

    // ---- write partial numerators ----
    float* pz = g_pacc[split];
    int lA = i0 + g, lB = lA + 8;
    if (lA < nrows) {
        float* pa = pz + ((long)(b*NN + rn_s[lA]))*DD + (tg << 1);
        #pragma unroll
        for (int nt = 0; nt < 8; nt++)
            *(float2*)&pa[nt << 3] = make_float2(acc[nt][0], acc[nt][1]);
    }
    if (lB < nrows) {
        float* pa = pz + ((long)(b*NN + rn_s[lB]))*DD + (tg << 1);
        #pragma unroll
        for (int nt = 0; nt < 8; nt++)
            *(float2*)&pa[nt << 3] = make_float2(acc[nt][2], acc[nt][3]);
    }
}

// ---------------- kernel 3: reduce partials, normalize, write out --------
__global__ __launch_bounds__(256) void k_reduce(float* __restrict__ out)
{
    int b = blockIdx.y;
    int k = blockIdx.x * 8 + (threadIdx.x >> 5);
    if (k >= g_cnt[b]) return;
    int lane = threadIdx.x & 31;
    int n = g_rows[b][k];
    long base = (long)b*NN + n;

    float z = 0.f;
    #pragma unroll
    for (int s = 0; s < JSPLIT; s++) z += g_pz[s][base];
    float inv = __fdividef(1.0f, z);

    long o = base*DD + lane*2;
    float vx = 0.f, vy = 0.f;
    #pragma unroll
    for (int s = 0; s < JSPLIT; s++) {
        float2 p = *(const float2*)&g_pacc[s][o];
        vx += p.x; vy += p.y;
    }
    *(float2*)&out[o] = make_float2(vx * inv, vy * inv);
}

// ---------------- launch ----------------
extern "C" void kernel_launch(void* const* d_in, const int* in_sizes, int n_in,
                              void* d_out, int out_size)
{
    const float* h     = (const float*)d_in[0];
    const int*   adj   = (const int*)  d_in[1];
    const float* hroot = (const float*)d_in[2];
    const float* W     = (const float*)d_in[3];
    const float* a1    = (const float*)d_in[4];
    const float* a2    = (const float*)d_in[5];
    float* out = (float*)d_out;

    k_reset<<<1, 32>>>();
    k_prep<<<BN/32, 256>>>(h, hroot, W, a1, a2, out);
    k_attn<<<dim3(NN/BLKR, JSPLIT, BB), 128>>>(adj);
    k_reduce<<<dim3(NN/8, BB), 256>>>(out);
}